// round 6
// baseline (speedup 1.0000x reference)
#include <cuda_runtime.h>
#include <cuda_bf16.h>
#include <math.h>
#include <stdint.h>

// Problem constants
#define BATCH   2
#define SEQLEN  2048
#define DMODEL  1024
#define DINNER  2048
#define DSTATE  16
#define DCONV   4
#define DTRANK  64
#define XDBL    (DTRANK + 2*DSTATE)   // 160
#define MROWS   (BATCH*SEQLEN)        // 4096

// ---------------------------------------------------------------------------
// Device-global scratch (no allocation allowed)
// ---------------------------------------------------------------------------
__device__ float g_xz  [MROWS * 2*DINNER];   // in_proj output
__device__ float g_xs  [MROWS * DINNER];     // conv+silu output (fp32 for scan)
__device__ float g_xdbl[MROWS * XDBL];       // x_proj output
__device__ float g_dt  [MROWS * DINNER];     // softplus dt (fp32 for scan)
__device__ float g_y   [MROWS * DINNER];     // scan output fp32

// Split-bf16 operands, 64-block-interleaved:
// per 64-col block i: A2 = [hi_i | hi_i | lo_i], B2 = [hi_i | lo_i | hi_i]
__device__ __nv_bfloat16 g_x2  [MROWS * 3*DMODEL];
__device__ __nv_bfloat16 g_w1_2[2*DINNER * 3*DMODEL];
__device__ __nv_bfloat16 g_xs2 [MROWS * 3*DINNER];
__device__ __nv_bfloat16 g_w3_2[XDBL * 3*DINNER];
__device__ __nv_bfloat16 g_dt2 [MROWS * 3*DTRANK];
__device__ __nv_bfloat16 g_w4_2[DINNER * 3*DTRANK];
__device__ __nv_bfloat16 g_y2  [MROWS * 3*DINNER];
__device__ __nv_bfloat16 g_w6_2[DMODEL * 3*DINNER];

// ---------------------------------------------------------------------------
// PTX helpers (baseline ISA: cp.async, ldmatrix, mma.sync)
// ---------------------------------------------------------------------------
__device__ __forceinline__ uint32_t smem_u32(const void* p) {
    uint32_t a;
    asm("{ .reg .u64 t; cvta.to.shared.u64 t, %1; cvt.u32.u64 %0, t; }"
        : "=r"(a) : "l"(p));
    return a;
}

#define CP_ASYNC16(dst, src) \
    asm volatile("cp.async.cg.shared.global [%0], [%1], 16;" :: "r"(dst), "l"(src) : "memory")
#define CP_COMMIT() asm volatile("cp.async.commit_group;" ::: "memory")
#define CP_WAIT2()  asm volatile("cp.async.wait_group 2;" ::: "memory")

#define LDSM4(r, addr) \
    asm volatile("ldmatrix.sync.aligned.m8n8.x4.shared.b16 {%0,%1,%2,%3}, [%4];" \
        : "=r"((r)[0]), "=r"((r)[1]), "=r"((r)[2]), "=r"((r)[3]) : "r"(addr))

#define MMA16816(c, a, b) \
    asm volatile("mma.sync.aligned.m16n8k16.row.col.f32.bf16.bf16.f32 " \
        "{%0,%1,%2,%3}, {%4,%5,%6,%7}, {%8,%9}, {%0,%1,%2,%3};" \
        : "+f"((c)[0]), "+f"((c)[1]), "+f"((c)[2]), "+f"((c)[3]) \
        : "r"((a)[0]), "r"((a)[1]), "r"((a)[2]), "r"((a)[3]), \
          "r"((b)[0]), "r"((b)[1]))

// ---------------------------------------------------------------------------
// Tensor-core GEMM: C[M, Nact] = A2[M, K2] * B2[Nact, K2]^T (bf16 in, fp32 out)
// Block tile 128x128, BK=64 (128B rows), 8 warps = 2(M) x 4(N), warp 64x32.
// 3-stage cp.async pipeline, swizzled smem, ldmatrix + mma.sync.
// NOTE: no min-blocks in launch_bounds — a reg cap of 128 caused spills.
// ---------------------------------------------------------------------------
#define STAGE_B 32768
#define GEMM_SMEM (3 * STAGE_B)

__global__ void __launch_bounds__(256)
gemm_mma(const __nv_bfloat16* __restrict__ A2,
         const __nv_bfloat16* __restrict__ B2,
         float* __restrict__ C, int ldc, int K2, int Nact,
         const float* __restrict__ bias, int mode)
{
    extern __shared__ char smem[];
    const uint32_t sb = smem_u32(smem);
    const int tid  = threadIdx.x;
    const int wid  = tid >> 5;
    const int lane = tid & 31;
    const int wm   = wid >> 2;       // 0..1
    const int wn   = wid & 3;        // 0..3
    const int mBase = blockIdx.y * 128;
    const int nBase = blockIdx.x * 128;

    // per-thread cp.async source: row r = tid>>1, half = tid&1 (64B each)
    const int r    = tid >> 1;
    const int half = tid & 1;
    const __nv_bfloat16* aSrcRow = A2 + (size_t)(mBase + r) * K2;
    int brow = nBase + r; if (brow >= Nact) brow = Nact - 1;
    const __nv_bfloat16* bSrcRow = B2 + (size_t)brow * K2;
    const uint32_t dstRowOff = (uint32_t)r * 128;
    const uint32_t rxor = (uint32_t)(r & 7) << 4;

    const int nch = K2 >> 6;

#define ISSUE(c, buf) do {                                                    \
    const char* as = (const char*)aSrcRow + (size_t)(c) * 128 + half * 64;    \
    const char* bs = (const char*)bSrcRow + (size_t)(c) * 128 + half * 64;    \
    uint32_t abuf = sb + (uint32_t)(buf) * STAGE_B;                           \
    uint32_t bbuf = abuf + 16384;                                             \
    _Pragma("unroll")                                                         \
    for (int u = 0; u < 4; u++) {                                             \
        uint32_t boff = (uint32_t)(half * 64 + u * 16) ^ rxor;                \
        CP_ASYNC16(abuf + dstRowOff + boff, as + u * 16);                     \
        CP_ASYNC16(bbuf + dstRowOff + boff, bs + u * 16);                     \
    }                                                                         \
} while (0)

    float acc[4][4][4];
#pragma unroll
    for (int i = 0; i < 4; i++)
#pragma unroll
        for (int j = 0; j < 4; j++)
#pragma unroll
            for (int k = 0; k < 4; k++) acc[i][j][k] = 0.f;

    const uint32_t lrow  = lane & 15;
    const uint32_t lsel  = (lane >> 4) * 16;          // k-half select (bytes)
    const uint32_t lxor  = (uint32_t)(lane & 7) << 4; // swizzle for addressed row

    // prologue: fill 3 stages
    ISSUE(0, 0); CP_COMMIT();
    if (nch > 1) ISSUE(1, 1);
    CP_COMMIT();
    if (nch > 2) ISSUE(2, 2);
    CP_COMMIT();

    int buf = 0;
    for (int c = 0; c < nch; c++) {
        CP_WAIT2();                 // group c complete
        __syncthreads();

        const uint32_t abuf = sb + (uint32_t)buf * STAGE_B;
        const uint32_t bbuf = abuf + 16384;
        const uint32_t aRow = abuf + (wm * 64 + lrow) * 128;
        const uint32_t bRow = bbuf + (wn * 32 + lrow) * 128;

#pragma unroll
        for (int s = 0; s < 4; s++) {
            const uint32_t kb = ((uint32_t)(s * 32) + lsel) ^ lxor;
            uint32_t aF[4][4];
            uint32_t bF[4][2];
#pragma unroll
            for (int mt = 0; mt < 4; mt++)
                LDSM4(aF[mt], aRow + mt * 2048 + kb);
#pragma unroll
            for (int nh = 0; nh < 2; nh++) {
                uint32_t t[4];
                LDSM4(t, bRow + nh * 2048 + kb);
                // x4 order: t0=(n0-7,kL) t1=(n8-15,kL) t2=(n0-7,kH) t3=(n8-15,kH)
                bF[nh * 2 + 0][0] = t[0]; bF[nh * 2 + 0][1] = t[2];
                bF[nh * 2 + 1][0] = t[1]; bF[nh * 2 + 1][1] = t[3];
            }
#pragma unroll
            for (int mt = 0; mt < 4; mt++)
#pragma unroll
                for (int nt = 0; nt < 4; nt++)
                    MMA16816(acc[mt][nt], aF[mt], bF[nt]);
        }
        __syncthreads();            // all warps done with `buf` before refill
        if (c + 3 < nch) ISSUE(c + 3, buf);
        CP_COMMIT();
        buf = (buf == 2) ? 0 : buf + 1;
    }

    // Epilogue
    const int er0 = mBase + wm * 64 + (lane >> 2);
    const int ec0 = nBase + wn * 32 + (lane & 3) * 2;
#pragma unroll
    for (int mt = 0; mt < 4; mt++) {
#pragma unroll
        for (int nt = 0; nt < 4; nt++) {
            int col = ec0 + nt * 8;
#pragma unroll
            for (int h = 0; h < 2; h++) {
                int row = er0 + mt * 16 + h * 8;
                float v0 = acc[mt][nt][h * 2 + 0];
                float v1 = acc[mt][nt][h * 2 + 1];
                if (mode == 1) {
                    if (col < Nact) {
                        v0 += bias[col];
                        v0 = (v0 > 20.f) ? v0 : log1pf(expf(v0));
                    }
                    if (col + 1 < Nact) {
                        v1 += bias[col + 1];
                        v1 = (v1 > 20.f) ? v1 : log1pf(expf(v1));
                    }
                }
                float* cp = C + (size_t)row * ldc + col;
                if (col + 1 < Nact) {
                    *(float2*)cp = make_float2(v0, v1);
                } else if (col < Nact) {
                    cp[0] = v0;
                }
            }
        }
    }
#undef ISSUE
}

// ---------------------------------------------------------------------------
// Split kernels: fp32 -> 64-block-interleaved bf16 layouts, fully coalesced.
// ---------------------------------------------------------------------------
__device__ __forceinline__ void split2(float2 v, __nv_bfloat162& hh, __nv_bfloat162& ll)
{
    __nv_bfloat16 h0 = __float2bfloat16(v.x);
    __nv_bfloat16 h1 = __float2bfloat16(v.y);
    __nv_bfloat16 l0 = __float2bfloat16(v.x - __bfloat162float(h0));
    __nv_bfloat16 l1 = __float2bfloat16(v.y - __bfloat162float(h1));
    hh = __nv_bfloat162(h0, h1);
    ll = __nv_bfloat162(l0, l1);
}

__global__ void split_A(const float* __restrict__ in, __nv_bfloat16* __restrict__ out,
                        int K, int total2)   // total2 = R*K/2
{
    int i = blockIdx.x * blockDim.x + threadIdx.x;
    if (i >= total2) return;
    int kh = K >> 1;
    int r = i / kh, c = (i - r * kh) * 2;
    __nv_bfloat162 hh, ll;
    split2(*(const float2*)(in + (size_t)r * K + c), hh, ll);
    __nv_bfloat162* o = (__nv_bfloat162*)(out + (size_t)r * 3 * K + (c >> 6) * 192 + (c & 63));
    o[0] = hh; o[32] = hh; o[64] = ll;
}

__global__ void split_B(const float* __restrict__ in, __nv_bfloat16* __restrict__ out,
                        int K, int total2)
{
    int i = blockIdx.x * blockDim.x + threadIdx.x;
    if (i >= total2) return;
    int kh = K >> 1;
    int r = i / kh, c = (i - r * kh) * 2;
    __nv_bfloat162 hh, ll;
    split2(*(const float2*)(in + (size_t)r * K + c), hh, ll);
    __nv_bfloat162* o = (__nv_bfloat162*)(out + (size_t)r * 3 * K + (c >> 6) * 192 + (c & 63));
    o[0] = hh; o[32] = ll; o[64] = hh;
}

// x_dbl[:, :DTRANK] (row stride XDBL) -> g_dt2 [MROWS, 192] A-type (K=64, 1 block)
__global__ void split_dtrank()
{
    int i = blockIdx.x * blockDim.x + threadIdx.x;
    if (i >= MROWS * 32) return;
    int r = i >> 5, c = (i & 31) * 2;
    __nv_bfloat162 hh, ll;
    split2(*(const float2*)(g_xdbl + (size_t)r * XDBL + c), hh, ll);
    __nv_bfloat162* o = (__nv_bfloat162*)(g_dt2 + (size_t)r * 192 + c);
    o[0] = hh; o[32] = hh; o[64] = ll;
}

// ---------------------------------------------------------------------------
// Depthwise causal conv (k=4) + bias + SiLU -> g_xs (fp32) + g_xs2 (A-split)
// ---------------------------------------------------------------------------
__global__ void conv_silu(const float* __restrict__ conv_w,
                          const float* __restrict__ conv_b)
{
    int i = blockIdx.x * blockDim.x + threadIdx.x;       // over MROWS*DINNER/2
    if (i >= MROWS * DINNER / 2) return;
    int dh = i % (DINNER / 2);
    int row = i / (DINNER / 2);
    int d = dh * 2;
    int l = row % SEQLEN;
    int b = row / SEQLEN;

    float acc0 = conv_b[d];
    float acc1 = conv_b[d + 1];
    const float* xi = g_xz + ((size_t)b * SEQLEN) * (2 * DINNER) + d;
    const float* w0 = conv_w + d * DCONV;
    const float* w1 = conv_w + (d + 1) * DCONV;
#pragma unroll
    for (int j = 0; j < DCONV; j++) {
        int ll = l - (DCONV - 1) + j;
        if (ll >= 0) {
            float2 xv = *(const float2*)(xi + (size_t)ll * (2 * DINNER));
            acc0 += xv.x * w0[j];
            acc1 += xv.y * w1[j];
        }
    }
    float s0 = acc0 / (1.f + __expf(-acc0));
    float s1 = acc1 / (1.f + __expf(-acc1));
    *(float2*)(g_xs + (size_t)row * DINNER + d) = make_float2(s0, s1);

    __nv_bfloat162 hh, ll2;
    split2(make_float2(s0, s1), hh, ll2);
    __nv_bfloat162* o = (__nv_bfloat162*)(g_xs2 + (size_t)row * 3 * DINNER + (d >> 6) * 192 + (d & 63));
    o[0] = hh; o[32] = hh; o[64] = ll2;
}

// ---------------------------------------------------------------------------
// Selective scan: warp = 2 channels x 16 state lanes; writes fp32 g_y.
// ---------------------------------------------------------------------------
__global__ void scan_kernel(const float* __restrict__ A_log,
                            const float* __restrict__ Dv)
{
    int gwarp = (blockIdx.x * blockDim.x + threadIdx.x) >> 5;
    int lane  = threadIdx.x & 31;
    int n     = lane & 15;
    int half  = lane >> 4;
    int ch    = gwarp * 2 + half;
    if (ch >= BATCH * DINNER) return;
    int b = ch / DINNER;
    int d = ch % DINNER;

    float a  = -expf(A_log[d * DSTATE + n]);
    float Dd = Dv[d];
    float h  = 0.f;

    const float* dt_p = g_dt   + (size_t)b * SEQLEN * DINNER + d;
    const float* xs_p = g_xs   + (size_t)b * SEQLEN * DINNER + d;
    const float* B_p  = g_xdbl + (size_t)b * SEQLEN * XDBL + DTRANK + n;
    const float* C_p  = B_p + DSTATE;
    const float* z_p  = g_xz   + (size_t)b * SEQLEN * (2 * DINNER) + DINNER + d;
    float*       y_p  = g_y    + (size_t)b * SEQLEN * DINNER + d;

    for (int l = 0; l < SEQLEN; l++) {
        float dtv = __ldg(dt_p);
        float xv  = __ldg(xs_p);
        float Bv  = __ldg(B_p);
        float Cv  = __ldg(C_p);

        float dA = __expf(dtv * a);
        h = dA * h + (dtv * xv) * Bv;
        float yv = h * Cv;

        yv += __shfl_xor_sync(0xFFFFFFFFu, yv, 8);
        yv += __shfl_xor_sync(0xFFFFFFFFu, yv, 4);
        yv += __shfl_xor_sync(0xFFFFFFFFu, yv, 2);
        yv += __shfl_xor_sync(0xFFFFFFFFu, yv, 1);

        if (n == 0) {
            float zv = __ldg(z_p);
            float gate = zv / (1.f + __expf(-zv));
            *y_p = (yv + xv * Dd) * gate;
        }

        dt_p += DINNER;
        xs_p += DINNER;
        B_p  += XDBL;
        C_p  += XDBL;
        z_p  += 2 * DINNER;
        y_p  += DINNER;
    }
}

// ---------------------------------------------------------------------------
extern "C" void kernel_launch(void* const* d_in, const int* in_sizes, int n_in,
                              void* d_out, int out_size)
{
    const float* x         = (const float*)d_in[0];
    const float* in_proj_w = (const float*)d_in[1];
    const float* conv_w    = (const float*)d_in[2];
    const float* conv_b    = (const float*)d_in[3];
    const float* x_proj_w  = (const float*)d_in[4];
    const float* dt_proj_w = (const float*)d_in[5];
    const float* dt_proj_b = (const float*)d_in[6];
    const float* A_log     = (const float*)d_in[7];
    const float* Dv        = (const float*)d_in[8];
    const float* out_proj_w= (const float*)d_in[9];
    float* out = (float*)d_out;

    cudaFuncSetAttribute(gemm_mma, cudaFuncAttributeMaxDynamicSharedMemorySize, GEMM_SMEM);

    float *xz, *xdbl, *dt, *y;
    __nv_bfloat16 *x2, *w1_2, *xs2, *w3_2, *dt2, *w4_2, *y2, *w6_2;
    cudaGetSymbolAddress((void**)&xz,   g_xz);
    cudaGetSymbolAddress((void**)&xdbl, g_xdbl);
    cudaGetSymbolAddress((void**)&dt,   g_dt);
    cudaGetSymbolAddress((void**)&y,    g_y);
    cudaGetSymbolAddress((void**)&x2,   g_x2);
    cudaGetSymbolAddress((void**)&w1_2, g_w1_2);
    cudaGetSymbolAddress((void**)&xs2,  g_xs2);
    cudaGetSymbolAddress((void**)&w3_2, g_w3_2);
    cudaGetSymbolAddress((void**)&dt2,  g_dt2);
    cudaGetSymbolAddress((void**)&w4_2, g_w4_2);
    cudaGetSymbolAddress((void**)&y2,   g_y2);
    cudaGetSymbolAddress((void**)&w6_2, g_w6_2);

    const int T = 256;
    // Launch order arranged so the ncu capture slot (4th launch) hits GEMM1.
    split_A<<<(MROWS*DMODEL/2 + T-1)/T, T>>>(x, x2, DMODEL, MROWS*DMODEL/2);
    split_B<<<(2*DINNER*DMODEL/2 + T-1)/T, T>>>(in_proj_w, w1_2, DMODEL, 2*DINNER*DMODEL/2);
    split_B<<<(DMODEL*DINNER/2 + T-1)/T, T>>>(out_proj_w, w6_2, DINNER, DMODEL*DINNER/2);

    // 1) xz = x @ in_proj_w^T   (4096 x 4096, K2=3072)   [4th launch -> profiled]
    gemm_mma<<<dim3(2*DINNER/128, MROWS/128), 256, GEMM_SMEM>>>(
        x2, w1_2, xz, 2*DINNER, 3*DMODEL, 2*DINNER, nullptr, 0);

    split_B<<<(XDBL*DINNER/2 + T-1)/T, T>>>(x_proj_w, w3_2, DINNER, XDBL*DINNER/2);
    split_B<<<(DINNER*DTRANK/2 + T-1)/T, T>>>(dt_proj_w, w4_2, DTRANK, DINNER*DTRANK/2);

    // 2) conv + SiLU
    conv_silu<<<(MROWS*DINNER/2 + T-1)/T, T>>>(conv_w, conv_b);

    // 3) x_dbl = xs @ x_proj_w^T  (4096 x 160, K2=6144)
    gemm_mma<<<dim3(2, MROWS/128), 256, GEMM_SMEM>>>(
        xs2, w3_2, xdbl, XDBL, 3*DINNER, XDBL, nullptr, 0);

    // 3b) split dt-rank slice
    split_dtrank<<<(MROWS*32 + T-1)/T, T>>>();

    // 4) dt = softplus(x_dbl[:,:64] @ dt_proj_w^T + b)  (4096 x 2048, K2=192)
    gemm_mma<<<dim3(DINNER/128, MROWS/128), 256, GEMM_SMEM>>>(
        dt2, w4_2, dt, DINNER, 3*DTRANK, DINNER, dt_proj_b, 1);

    // 5) selective scan -> y (fp32)
    scan_kernel<<<(BATCH*DINNER/2)*32/256, 256>>>(A_log, Dv);

    // 5b) split y (coalesced)
    split_A<<<(MROWS*DINNER/2 + T-1)/T, T>>>(y, y2, DINNER, MROWS*DINNER/2);

    // 6) out = y @ out_proj_w^T  (4096 x 1024, K2=6144)
    gemm_mma<<<dim3(DMODEL/128, MROWS/128), 256, GEMM_SMEM>>>(
        y2, w6_2, out, DMODEL, 3*DINNER, DMODEL, nullptr, 0);
}

// round 7
// speedup vs baseline: 1.8404x; 1.8404x over previous
#include <cuda_runtime.h>
#include <cuda_bf16.h>
#include <math.h>
#include <stdint.h>

// Problem constants
#define BATCH   2
#define SEQLEN  2048
#define DMODEL  1024
#define DINNER  2048
#define DSTATE  16
#define DCONV   4
#define DTRANK  64
#define XDBL    (DTRANK + 2*DSTATE)   // 160
#define MROWS   (BATCH*SEQLEN)        // 4096

// scan chunking
#define NCH_SCAN 16
#define LC       (SEQLEN / NCH_SCAN)          // 128
#define CHN      (BATCH * DINNER * DSTATE)    // 65536 state lanes

// ---------------------------------------------------------------------------
// Device-global scratch (no allocation allowed)
// ---------------------------------------------------------------------------
__device__ float g_xz  [MROWS * 2*DINNER];   // in_proj output
__device__ float g_xs  [MROWS * DINNER];     // conv+silu output (fp32 for scan)
__device__ float g_xdbl[MROWS * XDBL];       // x_proj output
__device__ float g_dt  [MROWS * DINNER];     // softplus dt (fp32 for scan)
__device__ float g_y   [MROWS * DINNER];     // scan output fp32

// chunked-scan intermediates
__device__ float g_P [NCH_SCAN * CHN];       // per-chunk prod(dA)
__device__ float g_S [NCH_SCAN * CHN];       // per-chunk local scan end-state
__device__ float g_H [NCH_SCAN * CHN];       // per-chunk initial state

// Split-bf16 operands, 64-block-interleaved:
// per 64-col block i: A2 = [hi_i | hi_i | lo_i], B2 = [hi_i | lo_i | hi_i]
__device__ __nv_bfloat16 g_x2  [MROWS * 3*DMODEL];
__device__ __nv_bfloat16 g_w1_2[2*DINNER * 3*DMODEL];
__device__ __nv_bfloat16 g_xs2 [MROWS * 3*DINNER];
__device__ __nv_bfloat16 g_w3_2[XDBL * 3*DINNER];
__device__ __nv_bfloat16 g_dt2 [MROWS * 3*DTRANK];
__device__ __nv_bfloat16 g_w4_2[DINNER * 3*DTRANK];
__device__ __nv_bfloat16 g_y2  [MROWS * 3*DINNER];
__device__ __nv_bfloat16 g_w6_2[DMODEL * 3*DINNER];

// ---------------------------------------------------------------------------
// PTX helpers (baseline ISA: cp.async, ldmatrix, mma.sync)
// ---------------------------------------------------------------------------
__device__ __forceinline__ uint32_t smem_u32(const void* p) {
    uint32_t a;
    asm("{ .reg .u64 t; cvta.to.shared.u64 t, %1; cvt.u32.u64 %0, t; }"
        : "=r"(a) : "l"(p));
    return a;
}

#define CP_ASYNC16(dst, src) \
    asm volatile("cp.async.cg.shared.global [%0], [%1], 16;" :: "r"(dst), "l"(src) : "memory")
#define CP_COMMIT() asm volatile("cp.async.commit_group;" ::: "memory")
#define CP_WAIT2()  asm volatile("cp.async.wait_group 2;" ::: "memory")

#define LDSM4(r, addr) \
    asm volatile("ldmatrix.sync.aligned.m8n8.x4.shared.b16 {%0,%1,%2,%3}, [%4];" \
        : "=r"((r)[0]), "=r"((r)[1]), "=r"((r)[2]), "=r"((r)[3]) : "r"(addr))

#define MMA16816(c, a, b) \
    asm volatile("mma.sync.aligned.m16n8k16.row.col.f32.bf16.bf16.f32 " \
        "{%0,%1,%2,%3}, {%4,%5,%6,%7}, {%8,%9}, {%0,%1,%2,%3};" \
        : "+f"((c)[0]), "+f"((c)[1]), "+f"((c)[2]), "+f"((c)[3]) \
        : "r"((a)[0]), "r"((a)[1]), "r"((a)[2]), "r"((a)[3]), \
          "r"((b)[0]), "r"((b)[1]))

// ---------------------------------------------------------------------------
// Tensor-core GEMM: C[M, Nact] = A2[M, K2] * B2[Nact, K2]^T (bf16 in, fp32 out)
// Block tile 128x128, BK=64 (128B rows), 8 warps = 2(M) x 4(N), warp 64x32.
// 3-stage cp.async pipeline, swizzled smem, ldmatrix + mma.sync.
// ---------------------------------------------------------------------------
#define STAGE_B 32768
#define GEMM_SMEM (3 * STAGE_B)

__global__ void __launch_bounds__(256)
gemm_mma(const __nv_bfloat16* __restrict__ A2,
         const __nv_bfloat16* __restrict__ B2,
         float* __restrict__ C, int ldc, int K2, int Nact,
         const float* __restrict__ bias, int mode)
{
    extern __shared__ char smem[];
    const uint32_t sb = smem_u32(smem);
    const int tid  = threadIdx.x;
    const int wid  = tid >> 5;
    const int lane = tid & 31;
    const int wm   = wid >> 2;       // 0..1
    const int wn   = wid & 3;        // 0..3
    const int mBase = blockIdx.y * 128;
    const int nBase = blockIdx.x * 128;

    // per-thread cp.async source: row r = tid>>1, half = tid&1 (64B each)
    const int r    = tid >> 1;
    const int half = tid & 1;
    const __nv_bfloat16* aSrcRow = A2 + (size_t)(mBase + r) * K2;
    int brow = nBase + r; if (brow >= Nact) brow = Nact - 1;
    const __nv_bfloat16* bSrcRow = B2 + (size_t)brow * K2;
    const uint32_t dstRowOff = (uint32_t)r * 128;
    const uint32_t rxor = (uint32_t)(r & 7) << 4;

    const int nch = K2 >> 6;

#define ISSUE(c, buf) do {                                                    \
    const char* as = (const char*)aSrcRow + (size_t)(c) * 128 + half * 64;    \
    const char* bs = (const char*)bSrcRow + (size_t)(c) * 128 + half * 64;    \
    uint32_t abuf = sb + (uint32_t)(buf) * STAGE_B;                           \
    uint32_t bbuf = abuf + 16384;                                             \
    _Pragma("unroll")                                                         \
    for (int u = 0; u < 4; u++) {                                             \
        uint32_t boff = (uint32_t)(half * 64 + u * 16) ^ rxor;                \
        CP_ASYNC16(abuf + dstRowOff + boff, as + u * 16);                     \
        CP_ASYNC16(bbuf + dstRowOff + boff, bs + u * 16);                     \
    }                                                                         \
} while (0)

    float acc[4][4][4];
#pragma unroll
    for (int i = 0; i < 4; i++)
#pragma unroll
        for (int j = 0; j < 4; j++)
#pragma unroll
            for (int k = 0; k < 4; k++) acc[i][j][k] = 0.f;

    const uint32_t lrow  = lane & 15;
    const uint32_t lsel  = (lane >> 4) * 16;          // k-half select (bytes)
    const uint32_t lxor  = (uint32_t)(lane & 7) << 4; // swizzle for addressed row

    // hoisted per-stage ldmatrix row bases
    const uint32_t aOff = (wm * 64 + lrow) * 128;
    const uint32_t bOff = 16384 + (wn * 32 + lrow) * 128;
    const uint32_t aRowS[3] = { sb + aOff, sb + STAGE_B + aOff, sb + 2*STAGE_B + aOff };
    const uint32_t bRowS[3] = { sb + bOff, sb + STAGE_B + bOff, sb + 2*STAGE_B + bOff };

    // prologue: fill 3 stages
    ISSUE(0, 0); CP_COMMIT();
    if (nch > 1) ISSUE(1, 1);
    CP_COMMIT();
    if (nch > 2) ISSUE(2, 2);
    CP_COMMIT();

    int buf = 0;
    for (int c = 0; c < nch; c++) {
        CP_WAIT2();                 // group c complete
        __syncthreads();

        const uint32_t aRow = aRowS[buf];
        const uint32_t bRow = bRowS[buf];

#pragma unroll
        for (int s = 0; s < 4; s++) {
            const uint32_t kb = ((uint32_t)(s * 32) + lsel) ^ lxor;
            uint32_t aF[4][4];
            uint32_t bF[4][2];
#pragma unroll
            for (int mt = 0; mt < 4; mt++)
                LDSM4(aF[mt], aRow + mt * 2048 + kb);
#pragma unroll
            for (int nh = 0; nh < 2; nh++) {
                uint32_t t[4];
                LDSM4(t, bRow + nh * 2048 + kb);
                // x4 order: t0=(n0-7,kL) t1=(n8-15,kL) t2=(n0-7,kH) t3=(n8-15,kH)
                bF[nh * 2 + 0][0] = t[0]; bF[nh * 2 + 0][1] = t[2];
                bF[nh * 2 + 1][0] = t[1]; bF[nh * 2 + 1][1] = t[3];
            }
#pragma unroll
            for (int mt = 0; mt < 4; mt++)
#pragma unroll
                for (int nt = 0; nt < 4; nt++)
                    MMA16816(acc[mt][nt], aF[mt], bF[nt]);
        }
        __syncthreads();            // all warps done with `buf` before refill
        if (c + 3 < nch) ISSUE(c + 3, buf);
        CP_COMMIT();
        buf = (buf == 2) ? 0 : buf + 1;
    }

    // Epilogue
    const int er0 = mBase + wm * 64 + (lane >> 2);
    const int ec0 = nBase + wn * 32 + (lane & 3) * 2;
#pragma unroll
    for (int mt = 0; mt < 4; mt++) {
#pragma unroll
        for (int nt = 0; nt < 4; nt++) {
            int col = ec0 + nt * 8;
#pragma unroll
            for (int h = 0; h < 2; h++) {
                int row = er0 + mt * 16 + h * 8;
                float v0 = acc[mt][nt][h * 2 + 0];
                float v1 = acc[mt][nt][h * 2 + 1];
                if (mode == 1) {
                    if (col < Nact) {
                        v0 += bias[col];
                        v0 = (v0 > 20.f) ? v0 : log1pf(expf(v0));
                    }
                    if (col + 1 < Nact) {
                        v1 += bias[col + 1];
                        v1 = (v1 > 20.f) ? v1 : log1pf(expf(v1));
                    }
                }
                float* cp = C + (size_t)row * ldc + col;
                if (col + 1 < Nact) {
                    *(float2*)cp = make_float2(v0, v1);
                } else if (col < Nact) {
                    cp[0] = v0;
                }
            }
        }
    }
#undef ISSUE
}

// ---------------------------------------------------------------------------
// Split kernels: fp32 -> 64-block-interleaved bf16 layouts, fully coalesced.
// ---------------------------------------------------------------------------
__device__ __forceinline__ void split2(float2 v, __nv_bfloat162& hh, __nv_bfloat162& ll)
{
    __nv_bfloat16 h0 = __float2bfloat16(v.x);
    __nv_bfloat16 h1 = __float2bfloat16(v.y);
    __nv_bfloat16 l0 = __float2bfloat16(v.x - __bfloat162float(h0));
    __nv_bfloat16 l1 = __float2bfloat16(v.y - __bfloat162float(h1));
    hh = __nv_bfloat162(h0, h1);
    ll = __nv_bfloat162(l0, l1);
}

__global__ void split_A(const float* __restrict__ in, __nv_bfloat16* __restrict__ out,
                        int K, int total2)   // total2 = R*K/2
{
    int i = blockIdx.x * blockDim.x + threadIdx.x;
    if (i >= total2) return;
    int kh = K >> 1;
    int r = i / kh, c = (i - r * kh) * 2;
    __nv_bfloat162 hh, ll;
    split2(*(const float2*)(in + (size_t)r * K + c), hh, ll);
    __nv_bfloat162* o = (__nv_bfloat162*)(out + (size_t)r * 3 * K + (c >> 6) * 192 + (c & 63));
    o[0] = hh; o[32] = hh; o[64] = ll;
}

__global__ void split_B(const float* __restrict__ in, __nv_bfloat16* __restrict__ out,
                        int K, int total2)
{
    int i = blockIdx.x * blockDim.x + threadIdx.x;
    if (i >= total2) return;
    int kh = K >> 1;
    int r = i / kh, c = (i - r * kh) * 2;
    __nv_bfloat162 hh, ll;
    split2(*(const float2*)(in + (size_t)r * K + c), hh, ll);
    __nv_bfloat162* o = (__nv_bfloat162*)(out + (size_t)r * 3 * K + (c >> 6) * 192 + (c & 63));
    o[0] = hh; o[32] = ll; o[64] = hh;
}

// x_dbl[:, :DTRANK] (row stride XDBL) -> g_dt2 [MROWS, 192] A-type (K=64, 1 block)
__global__ void split_dtrank()
{
    int i = blockIdx.x * blockDim.x + threadIdx.x;
    if (i >= MROWS * 32) return;
    int r = i >> 5, c = (i & 31) * 2;
    __nv_bfloat162 hh, ll;
    split2(*(const float2*)(g_xdbl + (size_t)r * XDBL + c), hh, ll);
    __nv_bfloat162* o = (__nv_bfloat162*)(g_dt2 + (size_t)r * 192 + c);
    o[0] = hh; o[32] = hh; o[64] = ll;
}

// ---------------------------------------------------------------------------
// Depthwise causal conv (k=4) + bias + SiLU -> g_xs (fp32) + g_xs2 (A-split)
// ---------------------------------------------------------------------------
__global__ void conv_silu(const float* __restrict__ conv_w,
                          const float* __restrict__ conv_b)
{
    int i = blockIdx.x * blockDim.x + threadIdx.x;       // over MROWS*DINNER/2
    if (i >= MROWS * DINNER / 2) return;
    int dh = i % (DINNER / 2);
    int row = i / (DINNER / 2);
    int d = dh * 2;
    int l = row % SEQLEN;
    int b = row / SEQLEN;

    float acc0 = conv_b[d];
    float acc1 = conv_b[d + 1];
    const float* xi = g_xz + ((size_t)b * SEQLEN) * (2 * DINNER) + d;
    const float* w0 = conv_w + d * DCONV;
    const float* w1 = conv_w + (d + 1) * DCONV;
#pragma unroll
    for (int j = 0; j < DCONV; j++) {
        int ll = l - (DCONV - 1) + j;
        if (ll >= 0) {
            float2 xv = *(const float2*)(xi + (size_t)ll * (2 * DINNER));
            acc0 += xv.x * w0[j];
            acc1 += xv.y * w1[j];
        }
    }
    float s0 = acc0 / (1.f + __expf(-acc0));
    float s1 = acc1 / (1.f + __expf(-acc1));
    *(float2*)(g_xs + (size_t)row * DINNER + d) = make_float2(s0, s1);

    __nv_bfloat162 hh, ll2;
    split2(make_float2(s0, s1), hh, ll2);
    __nv_bfloat162* o = (__nv_bfloat162*)(g_xs2 + (size_t)row * 3 * DINNER + (d >> 6) * 192 + (d & 63));
    o[0] = hh; o[32] = hh; o[64] = ll2;
}

// ---------------------------------------------------------------------------
// Chunked parallel scan (3 passes).
// Warp layout per chunk: 2 channels x 16 state lanes (same as monolithic scan).
// State index for lane: idx = ch*DSTATE + n  (coalesced per warp).
// ---------------------------------------------------------------------------
__global__ void scan_p1(const float* __restrict__ A_log)
{
    int gw   = (blockIdx.x * blockDim.x + threadIdx.x) >> 5;
    int lane = threadIdx.x & 31;
    int j    = gw >> 11;             // chunk (2048 warps per chunk)
    int ch2  = gw & 2047;
    int n    = lane & 15;
    int ch   = ch2 * 2 + (lane >> 4);
    int b    = ch >> 11;             // / DINNER
    int d    = ch & 2047;

    float a = -expf(A_log[d * DSTATE + n]);
    float h = 0.f, p = 1.f;

    const int l0 = j * LC;
    const float* dt_p = g_dt   + ((size_t)b * SEQLEN + l0) * DINNER + d;
    const float* xs_p = g_xs   + ((size_t)b * SEQLEN + l0) * DINNER + d;
    const float* B_p  = g_xdbl + ((size_t)b * SEQLEN + l0) * XDBL + DTRANK + n;

#pragma unroll 4
    for (int t = 0; t < LC; t++) {
        float dtv = __ldg(dt_p);
        float xv  = __ldg(xs_p);
        float Bv  = __ldg(B_p);
        float dA  = __expf(dtv * a);
        h = dA * h + (dtv * xv) * Bv;
        p *= dA;
        dt_p += DINNER; xs_p += DINNER; B_p += XDBL;
    }

    int idx = ch * DSTATE + n;
    g_S[(size_t)j * CHN + idx] = h;
    g_P[(size_t)j * CHN + idx] = p;
}

__global__ void scan_p2()
{
    int i = blockIdx.x * blockDim.x + threadIdx.x;   // < CHN
    float h = 0.f;
#pragma unroll
    for (int j = 0; j < NCH_SCAN; j++) {
        g_H[(size_t)j * CHN + i] = h;
        h = g_P[(size_t)j * CHN + i] * h + g_S[(size_t)j * CHN + i];
    }
}

__global__ void scan_p3(const float* __restrict__ A_log,
                        const float* __restrict__ Dv)
{
    int gw   = (blockIdx.x * blockDim.x + threadIdx.x) >> 5;
    int lane = threadIdx.x & 31;
    int j    = gw >> 11;
    int ch2  = gw & 2047;
    int n    = lane & 15;
    int ch   = ch2 * 2 + (lane >> 4);
    int b    = ch >> 11;
    int d    = ch & 2047;

    float a  = -expf(A_log[d * DSTATE + n]);
    float Dd = Dv[d];
    int idx  = ch * DSTATE + n;
    float h  = g_H[(size_t)j * CHN + idx];

    const int l0 = j * LC;
    const float* dt_p = g_dt   + ((size_t)b * SEQLEN + l0) * DINNER + d;
    const float* xs_p = g_xs   + ((size_t)b * SEQLEN + l0) * DINNER + d;
    const float* B_p  = g_xdbl + ((size_t)b * SEQLEN + l0) * XDBL + DTRANK + n;
    const float* C_p  = B_p + DSTATE;
    const float* z_p  = g_xz   + ((size_t)b * SEQLEN + l0) * (2 * DINNER) + DINNER + d;
    float*       y_p  = g_y    + ((size_t)b * SEQLEN + l0) * DINNER + d;

#pragma unroll 2
    for (int t = 0; t < LC; t++) {
        float dtv = __ldg(dt_p);
        float xv  = __ldg(xs_p);
        float Bv  = __ldg(B_p);
        float Cv  = __ldg(C_p);

        float dA = __expf(dtv * a);
        h = dA * h + (dtv * xv) * Bv;
        float yv = h * Cv;

        yv += __shfl_xor_sync(0xFFFFFFFFu, yv, 8);
        yv += __shfl_xor_sync(0xFFFFFFFFu, yv, 4);
        yv += __shfl_xor_sync(0xFFFFFFFFu, yv, 2);
        yv += __shfl_xor_sync(0xFFFFFFFFu, yv, 1);

        if (n == 0) {
            float zv = __ldg(z_p);
            float gate = zv / (1.f + __expf(-zv));
            *y_p = (yv + xv * Dd) * gate;
        }

        dt_p += DINNER; xs_p += DINNER; B_p += XDBL; C_p += XDBL;
        z_p += 2 * DINNER; y_p += DINNER;
    }
}

// ---------------------------------------------------------------------------
extern "C" void kernel_launch(void* const* d_in, const int* in_sizes, int n_in,
                              void* d_out, int out_size)
{
    const float* x         = (const float*)d_in[0];
    const float* in_proj_w = (const float*)d_in[1];
    const float* conv_w    = (const float*)d_in[2];
    const float* conv_b    = (const float*)d_in[3];
    const float* x_proj_w  = (const float*)d_in[4];
    const float* dt_proj_w = (const float*)d_in[5];
    const float* dt_proj_b = (const float*)d_in[6];
    const float* A_log     = (const float*)d_in[7];
    const float* Dv        = (const float*)d_in[8];
    const float* out_proj_w= (const float*)d_in[9];
    float* out = (float*)d_out;

    cudaFuncSetAttribute(gemm_mma, cudaFuncAttributeMaxDynamicSharedMemorySize, GEMM_SMEM);

    float *xz, *xdbl, *dt, *y;
    __nv_bfloat16 *x2, *w1_2, *xs2, *w3_2, *dt2, *w4_2, *y2, *w6_2;
    cudaGetSymbolAddress((void**)&xz,   g_xz);
    cudaGetSymbolAddress((void**)&xdbl, g_xdbl);
    cudaGetSymbolAddress((void**)&dt,   g_dt);
    cudaGetSymbolAddress((void**)&y,    g_y);
    cudaGetSymbolAddress((void**)&x2,   g_x2);
    cudaGetSymbolAddress((void**)&w1_2, g_w1_2);
    cudaGetSymbolAddress((void**)&xs2,  g_xs2);
    cudaGetSymbolAddress((void**)&w3_2, g_w3_2);
    cudaGetSymbolAddress((void**)&dt2,  g_dt2);
    cudaGetSymbolAddress((void**)&w4_2, g_w4_2);
    cudaGetSymbolAddress((void**)&y2,   g_y2);
    cudaGetSymbolAddress((void**)&w6_2, g_w6_2);

    const int T = 256;
    // Order keeps GEMM1 at the ncu capture slot (4th launch).
    split_A<<<(MROWS*DMODEL/2 + T-1)/T, T>>>(x, x2, DMODEL, MROWS*DMODEL/2);
    split_B<<<(2*DINNER*DMODEL/2 + T-1)/T, T>>>(in_proj_w, w1_2, DMODEL, 2*DINNER*DMODEL/2);
    split_B<<<(DMODEL*DINNER/2 + T-1)/T, T>>>(out_proj_w, w6_2, DINNER, DMODEL*DINNER/2);

    // 1) xz = x @ in_proj_w^T   (4096 x 4096, K2=3072)   [profiled launch]
    gemm_mma<<<dim3(2*DINNER/128, MROWS/128), 256, GEMM_SMEM>>>(
        x2, w1_2, xz, 2*DINNER, 3*DMODEL, 2*DINNER, nullptr, 0);

    split_B<<<(XDBL*DINNER/2 + T-1)/T, T>>>(x_proj_w, w3_2, DINNER, XDBL*DINNER/2);
    split_B<<<(DINNER*DTRANK/2 + T-1)/T, T>>>(dt_proj_w, w4_2, DTRANK, DINNER*DTRANK/2);

    // 2) conv + SiLU
    conv_silu<<<(MROWS*DINNER/2 + T-1)/T, T>>>(conv_w, conv_b);

    // 3) x_dbl = xs @ x_proj_w^T  (4096 x 160, K2=6144)
    gemm_mma<<<dim3(2, MROWS/128), 256, GEMM_SMEM>>>(
        xs2, w3_2, xdbl, XDBL, 3*DINNER, XDBL, nullptr, 0);

    // 3b) split dt-rank slice
    split_dtrank<<<(MROWS*32 + T-1)/T, T>>>();

    // 4) dt = softplus(x_dbl[:,:64] @ dt_proj_w^T + b)  (4096 x 2048, K2=192)
    gemm_mma<<<dim3(DINNER/128, MROWS/128), 256, GEMM_SMEM>>>(
        dt2, w4_2, dt, DINNER, 3*DTRANK, DINNER, dt_proj_b, 1);

    // 5) chunked parallel scan -> y (fp32)
    scan_p1<<<NCH_SCAN * 2048 * 32 / 256, 256>>>(A_log);
    scan_p2<<<CHN / 256, 256>>>();
    scan_p3<<<NCH_SCAN * 2048 * 32 / 256, 256>>>(A_log, Dv);

    // 5b) split y (coalesced)
    split_A<<<(MROWS*DINNER/2 + T-1)/T, T>>>(y, y2, DINNER, MROWS*DINNER/2);

    // 6) out = y @ out_proj_w^T  (4096 x 1024, K2=6144)
    gemm_mma<<<dim3(DMODEL/128, MROWS/128), 256, GEMM_SMEM>>>(
        y2, w6_2, out, DMODEL, 3*DINNER, DMODEL, nullptr, 0);
}